// round 13
// baseline (speedup 1.0000x reference)
#include <cuda_runtime.h>
#include <math_constants.h>

// Problem shape (fixed by reference): B=32, C=8, H=W=256
#define HM        256        // B*C heatmaps
#define HW        65536      // H*W elements per heatmap
#define SLICES    2          // blocks per heatmap
#define NBLK      (HM * SLICES)          // 512 blocks -> ONE wave (4/SM x 148)
#define SLICE_EL  (HW / SLICES)          // 32768 elements per slice
#define T1        512                    // threads per block
#define V4_PER_T  (SLICE_EL / 4 / T1)    // 16 float4 quads / thread / tensor

// Scratch (no device allocation allowed -> __device__ globals, zero-initialized)
__device__ float        g_s [NBLK];
__device__ float        g_sx[NBLK];
__device__ float        g_sy[NBLK];
__device__ float        g_bv[NBLK];
__device__ int          g_bi[NBLK];
__device__ unsigned int g_count;   // last-block-done ticket; reset each call

// Single-wave static partition: 512 blocks x 512 threads, 32 regs -> 4
// blocks/SM, all blocks resident simultaneously (no wave-quantization tail,
// no work-stealing overhead). Rolling loads + fused last-block epilogue with
// writer-only release fence (the proven protocol from R6).
__global__ __launch_bounds__(T1)
void dsnt_fused(const float* __restrict__ inp, const float* __restrict__ tgt,
                float* __restrict__ out) {
    const int blk = blockIdx.x;
    const int hm  = blk >> 1;       // heatmap id
    const int sl  = blk & 1;        // slice id
    const size_t base = (size_t)hm * HW + (size_t)sl * SLICE_EL;
    const float4* __restrict__ in4 = (const float4*)(inp + base);
    const float4* __restrict__ tg4 = (const float4*)(tgt + base);

    const int tid  = threadIdx.x;
    const int off0 = sl * SLICE_EL;      // element offset of slice within heatmap

    float s = 0.f, sx = 0.f, sy = 0.f;
    float bv = -CUDART_INF_F;
    int   bi = 0x7fffffff;

    #pragma unroll
    for (int it = 0; it < V4_PER_T; ++it) {
        const int i4  = tid + it * T1;       // coalesced float4 index in slice
        const float4 v = in4[i4];
        const float4 t = tg4[i4];
        const int off = off0 + i4 * 4;       // element index within heatmap
        const int h   = off >> 8;
        const int w   = off & 255;
        // xs[j] = (j+1-128)/256 = (j-127)/256 ; ys[p] = (p-127)/256
        const float y  = (float)(h - 127) * (1.0f / 256.0f);
        const float x0 = (float)(w - 127) * (1.0f / 256.0f);

        const float e0 = __expf(v.x);
        const float e1 = __expf(v.y);
        const float e2 = __expf(v.z);
        const float e3 = __expf(v.w);
        const float es = (e0 + e1) + (e2 + e3);
        s += es;
        sy = fmaf(y, es, sy);
        // sum e_k * x_{w+k} = x0*es + (e1 + 2e2 + 3e3)/256
        sx = fmaf(x0, es,
             fmaf(1.0f / 256.0f, fmaf(3.f, e3, fmaf(2.f, e2, e1)), sx));

        // argmax with FIRST-index tie-break: fmax tree + rare branch
        const float qmax = fmaxf(fmaxf(t.x, t.y), fmaxf(t.z, t.w));
        if (qmax > bv) {
            bv = qmax;
            bi = (t.x == qmax) ? off :
                 (t.y == qmax) ? off + 1 :
                 (t.z == qmax) ? off + 2 : off + 3;
        }
    }

    // warp reduction
    #pragma unroll
    for (int o = 16; o > 0; o >>= 1) {
        s  += __shfl_down_sync(0xffffffffu, s,  o);
        sx += __shfl_down_sync(0xffffffffu, sx, o);
        sy += __shfl_down_sync(0xffffffffu, sy, o);
        const float ov = __shfl_down_sync(0xffffffffu, bv, o);
        const int   oi = __shfl_down_sync(0xffffffffu, bi, o);
        if (ov > bv || (ov == bv && oi < bi)) { bv = ov; bi = oi; }
    }

    __shared__ float sh_s [T1 / 32];
    __shared__ float sh_sx[T1 / 32];
    __shared__ float sh_sy[T1 / 32];
    __shared__ float sh_bv[T1 / 32];
    __shared__ int   sh_bi[T1 / 32];
    __shared__ unsigned int sh_ticket;
    const int wid = tid >> 5, lid = tid & 31;
    if (lid == 0) {
        sh_s[wid] = s; sh_sx[wid] = sx; sh_sy[wid] = sy;
        sh_bv[wid] = bv; sh_bi[wid] = bi;
    }
    __syncthreads();

    if (wid == 0) {
        const bool ok = lid < (T1 / 32);
        s  = ok ? sh_s [lid] : 0.f;
        sx = ok ? sh_sx[lid] : 0.f;
        sy = ok ? sh_sy[lid] : 0.f;
        bv = ok ? sh_bv[lid] : -CUDART_INF_F;
        bi = ok ? sh_bi[lid] : 0x7fffffff;
        #pragma unroll
        for (int o = 8; o > 0; o >>= 1) {
            s  += __shfl_down_sync(0xffffffffu, s,  o);
            sx += __shfl_down_sync(0xffffffffu, sx, o);
            sy += __shfl_down_sync(0xffffffffu, sy, o);
            const float ov = __shfl_down_sync(0xffffffffu, bv, o);
            const int   oi = __shfl_down_sync(0xffffffffu, bi, o);
            if (ov > bv || (ov == bv && oi < bi)) { bv = ov; bi = oi; }
        }
        if (lid == 0) {
            // single writer: store partials, release-fence, take ticket
            g_s [blk] = s;
            g_sx[blk] = sx;
            g_sy[blk] = sy;
            g_bv[blk] = bv;
            g_bi[blk] = bi;
            __threadfence();                       // writer-only release
            sh_ticket = atomicAdd(&g_count, 1u);
        }
    }
    __syncthreads();
    if (sh_ticket != NBLK - 1) return;   // not the last block

    // ---- last-block epilogue (256 reading threads) ----
    float m = 0.f;
    if (tid < HM) {
        __threadfence();                 // reader-side acquire (8 warps only)
        float fs = 0.f, fsx = 0.f, fsy = 0.f;
        float fbv = -CUDART_INF_F;
        int   fbi = 0x7fffffff;
        #pragma unroll
        for (int k = 0; k < SLICES; ++k) {
            const int idx = tid * SLICES + k;
            fs  += __ldcg(&g_s [idx]);
            fsx += __ldcg(&g_sx[idx]);
            fsy += __ldcg(&g_sy[idx]);
            const float v = __ldcg(&g_bv[idx]);
            const int   i = __ldcg(&g_bi[idx]);
            if (v > fbv || (v == fbv && i < fbi)) { fbv = v; fbi = i; }
        }
        const float inv = 1.0f / fs;
        const float px = fsx * inv;
        const float py = fsy * inv;
        const float tx = (float)((fbi & 255) - 127) * (1.0f / 256.0f);
        const float ty = (float)((fbi >> 8)  - 127) * (1.0f / 256.0f);
        const float dx = px - tx;
        const float dy = py - ty;
        m = 0.5f * (dx * dx + dy * dy);
    }

    // fixed-order reduce of 256 values (tid 256..511 contribute 0)
    #pragma unroll
    for (int o = 16; o > 0; o >>= 1)
        m += __shfl_down_sync(0xffffffffu, m, o);
    __shared__ float sh_m[T1 / 32];
    if (lid == 0) sh_m[wid] = m;
    __syncthreads();
    if (tid == 0) {
        float tot = 0.f;
        #pragma unroll
        for (int w = 0; w < 8; ++w) tot += sh_m[w];   // heatmap warps 0..7 only
        out[0] = tot * (1.0f / 32.0f);                // divide by B
        g_count = 0;                                   // reset for next replay
    }
}

extern "C" void kernel_launch(void* const* d_in, const int* in_sizes, int n_in,
                              void* d_out, int out_size) {
    const float* inp = (const float*)d_in[0];
    const float* tgt = (const float*)d_in[1];
    float* out = (float*)d_out;
    (void)in_sizes; (void)n_in; (void)out_size;

    dsnt_fused<<<NBLK, T1>>>(inp, tgt, out);
}

// round 14
// speedup vs baseline: 1.0242x; 1.0242x over previous
#include <cuda_runtime.h>
#include <math_constants.h>

// Problem shape (fixed by reference): B=32, C=8, H=W=256
#define HM        256        // B*C heatmaps
#define HW        65536      // H*W elements per heatmap
#define SLICES    2          // blocks per heatmap
#define NBLK      (HM * SLICES)          // 512 blocks -> ONE wave (4/SM x 148)
#define SLICE_EL  (HW / SLICES)          // 32768 elements per slice
#define T1        512                    // threads per block
#define V4_PER_T  (SLICE_EL / 4 / T1)    // 16 float4 quads / thread / tensor

// Scratch (no device allocation allowed -> __device__ globals, zero-initialized)
__device__ float        g_s [NBLK];
__device__ float        g_sx[NBLK];
__device__ float        g_sy[NBLK];
__device__ float        g_bv[NBLK];
__device__ int          g_bi[NBLK];
__device__ float        g_m [HM];      // per-heatmap MSE (distributed fold)
__device__ unsigned int g_hmc[HM];     // per-heatmap pair tickets
__device__ unsigned int g_count;       // heatmaps-done ticket

// Single-wave static partition (best measured kernel config, R13) with:
//  - hoisted coordinate math: x-weight is a per-thread constant, y advances
//    by exactly 8 rows (0.03125) per iteration -> hot loop is loads+exp+fma.
//  - distributed fold: the 2nd-finishing block of each heatmap folds that
//    heatmap's two slices into g_m[hm] while other blocks still stream;
//    the 256th heatmap-finisher does only a 256-float fixed-order sum.
__global__ __launch_bounds__(T1)
void dsnt_fused(const float* __restrict__ inp, const float* __restrict__ tgt,
                float* __restrict__ out) {
    const int blk = blockIdx.x;
    const int hm  = blk >> 1;       // heatmap id
    const int sl  = blk & 1;        // slice id
    const size_t base = (size_t)hm * HW + (size_t)sl * SLICE_EL;
    const float4* __restrict__ in4 = (const float4*)(inp + base);
    const float4* __restrict__ tg4 = (const float4*)(tgt + base);

    const int tid  = threadIdx.x;
    const int off0 = sl * SLICE_EL;          // element offset within heatmap
    const int eoff = off0 + 4 * tid;         // this thread's first element idx

    // hoisted coordinates: w = (4*tid)&255 is per-thread constant;
    // h advances by 8 per iteration (stride 2048 elements = 8 rows).
    const float x0    = (float)(((4 * tid) & 255) - 127) * (1.0f / 256.0f);
    const float ybase = (float)((eoff >> 8) - 127) * (1.0f / 256.0f);

    float s = 0.f, sx = 0.f, sy = 0.f;
    float bv = -CUDART_INF_F;
    int   bi = 0x7fffffff;

    #pragma unroll
    for (int it = 0; it < V4_PER_T; ++it) {
        const float4 v = in4[tid + it * T1];
        const float4 t = tg4[tid + it * T1];
        const float  y = ybase + (float)it * 0.03125f;   // +8 rows / iter

        const float e0 = __expf(v.x);
        const float e1 = __expf(v.y);
        const float e2 = __expf(v.z);
        const float e3 = __expf(v.w);
        const float es = (e0 + e1) + (e2 + e3);
        s += es;
        sy = fmaf(y, es, sy);
        // sum e_k * x_{w+k} = x0*es + (e1 + 2e2 + 3e3)/256
        sx = fmaf(x0, es,
             fmaf(1.0f / 256.0f, fmaf(3.f, e3, fmaf(2.f, e2, e1)), sx));

        // target argmax with FIRST-index tie-break (rare branch)
        const float qmax = fmaxf(fmaxf(t.x, t.y), fmaxf(t.z, t.w));
        if (qmax > bv) {
            const int off = eoff + it * 2048;
            bv = qmax;
            bi = (t.x == qmax) ? off :
                 (t.y == qmax) ? off + 1 :
                 (t.z == qmax) ? off + 2 : off + 3;
        }
    }

    // warp reduction
    #pragma unroll
    for (int o = 16; o > 0; o >>= 1) {
        s  += __shfl_down_sync(0xffffffffu, s,  o);
        sx += __shfl_down_sync(0xffffffffu, sx, o);
        sy += __shfl_down_sync(0xffffffffu, sy, o);
        const float ov = __shfl_down_sync(0xffffffffu, bv, o);
        const int   oi = __shfl_down_sync(0xffffffffu, bi, o);
        if (ov > bv || (ov == bv && oi < bi)) { bv = ov; bi = oi; }
    }

    __shared__ float sh_s [T1 / 32];
    __shared__ float sh_sx[T1 / 32];
    __shared__ float sh_sy[T1 / 32];
    __shared__ float sh_bv[T1 / 32];
    __shared__ int   sh_bi[T1 / 32];
    __shared__ unsigned int sh_ticket;
    const int wid = tid >> 5, lid = tid & 31;
    if (lid == 0) {
        sh_s[wid] = s; sh_sx[wid] = sx; sh_sy[wid] = sy;
        sh_bv[wid] = bv; sh_bi[wid] = bi;
    }
    __syncthreads();

    if (wid == 0) {
        const bool ok = lid < (T1 / 32);
        s  = ok ? sh_s [lid] : 0.f;
        sx = ok ? sh_sx[lid] : 0.f;
        sy = ok ? sh_sy[lid] : 0.f;
        bv = ok ? sh_bv[lid] : -CUDART_INF_F;
        bi = ok ? sh_bi[lid] : 0x7fffffff;
        #pragma unroll
        for (int o = 8; o > 0; o >>= 1) {
            s  += __shfl_down_sync(0xffffffffu, s,  o);
            sx += __shfl_down_sync(0xffffffffu, sx, o);
            sy += __shfl_down_sync(0xffffffffu, sy, o);
            const float ov = __shfl_down_sync(0xffffffffu, bv, o);
            const int   oi = __shfl_down_sync(0xffffffffu, bi, o);
            if (ov > bv || (ov == bv && oi < bi)) { bv = ov; bi = oi; }
        }
        if (lid == 0) {
            // store this slice's partials, release, take the heatmap ticket
            g_s [blk] = s;
            g_sx[blk] = sx;
            g_sy[blk] = sy;
            g_bv[blk] = bv;
            g_bi[blk] = bi;
            __threadfence();                              // release partials
            unsigned int tk = 0xffffffffu;
            if (atomicAdd(&g_hmc[hm], 1u) == 1u) {
                // 2nd slice of this heatmap done -> fold NOW (overlapped
                // with other blocks still streaming)
                __threadfence();                          // acquire partials
                float fs = 0.f, fsx = 0.f, fsy = 0.f;
                float fbv = -CUDART_INF_F;
                int   fbi = 0x7fffffff;
                #pragma unroll
                for (int k = 0; k < SLICES; ++k) {        // fixed order
                    const int idx = hm * SLICES + k;
                    fs  += __ldcg(&g_s [idx]);
                    fsx += __ldcg(&g_sx[idx]);
                    fsy += __ldcg(&g_sy[idx]);
                    const float v = __ldcg(&g_bv[idx]);
                    const int   i = __ldcg(&g_bi[idx]);
                    if (v > fbv || (v == fbv && i < fbi)) { fbv = v; fbi = i; }
                }
                const float inv = 1.0f / fs;
                const float px = fsx * inv;
                const float py = fsy * inv;
                const float tx = (float)((fbi & 255) - 127) * (1.0f / 256.0f);
                const float ty = (float)((fbi >> 8)  - 127) * (1.0f / 256.0f);
                const float dx = px - tx;
                const float dy = py - ty;
                g_m[hm] = 0.5f * (dx * dx + dy * dy);
                __threadfence();                          // release g_m
                tk = atomicAdd(&g_count, 1u);
            }
            sh_ticket = tk;
        }
    }
    __syncthreads();
    if (sh_ticket != HM - 1) return;     // not the last heatmap-finisher

    // ---- final epilogue: fixed-order sum of 256 heatmap MSEs / B ----
    float m = 0.f;
    if (tid < HM) {
        __threadfence();                 // acquire g_m (8 warps only)
        m = __ldcg(&g_m[tid]);
        g_hmc[tid] = 0;                  // reset pair tickets for next replay
    }
    #pragma unroll
    for (int o = 16; o > 0; o >>= 1)
        m += __shfl_down_sync(0xffffffffu, m, o);
    __shared__ float sh_m[T1 / 32];
    if (lid == 0) sh_m[wid] = m;
    __syncthreads();
    if (tid == 0) {
        float tot = 0.f;
        #pragma unroll
        for (int w = 0; w < 8; ++w) tot += sh_m[w];   // warps 0..7 hold tids<256
        out[0] = tot * (1.0f / 32.0f);                // divide by B
        g_count = 0;                                   // reset for next replay
    }
}

extern "C" void kernel_launch(void* const* d_in, const int* in_sizes, int n_in,
                              void* d_out, int out_size) {
    const float* inp = (const float*)d_in[0];
    const float* tgt = (const float*)d_in[1];
    float* out = (float*)d_out;
    (void)in_sizes; (void)n_in; (void)out_size;

    dsnt_fused<<<NBLK, T1>>>(inp, tgt, out);
}